// round 3
// baseline (speedup 1.0000x reference)
#include <cuda_runtime.h>
#include <cuda_bf16.h>

#define NN 50000
#define EE 800000
#define FH 128

// ---------------- scratch (device globals; no allocation allowed) ----------------
__device__ int   g_is64;
__device__ int   g_degi[NN];
__device__ int   g_ptr[NN];
__device__ int   g_cursor[NN];
__device__ int   g_csrc[EE];
__device__ int   g_srci[EE];
__device__ int   g_dsti[EE];
__device__ float g_cat[(size_t)NN * 256];   // [agg | root] input to SAGE gemms
__device__ float g_h1[(size_t)NN * 128];
__device__ float g_h2[(size_t)NN * 128];
__device__ float g_AB[(size_t)NN * 512];    // cols 0..255 = A(+b3), 256..511 = B
__device__ float g_W[256 * 512];            // packed weight buffer (reused per stage)
__device__ float g_bias[512];

// ---------------- edge_index dtype detection (int32 vs int64) ----------------
// For int64 data, every odd 32-bit word (hi half) of values in [0, 50000) is 0.
// For int32 data, odd words are random indices — all-zero over 1024 samples ~ impossible.
__global__ void k_detect(const int* __restrict__ ei_raw) {
    __shared__ int nz;
    if (threadIdx.x == 0) nz = 0;
    __syncthreads();
    for (int i = threadIdx.x; i < 1024; i += blockDim.x)
        if (ei_raw[2 * i + 1] != 0) nz = 1;
    __syncthreads();
    if (threadIdx.x == 0) g_is64 = (nz == 0) ? 1 : 0;
}

// ---------------- CSR construction ----------------
__global__ void k_init() {
    int i = blockIdx.x * blockDim.x + threadIdx.x;
    if (i < NN) { g_degi[i] = 0; g_cursor[i] = 0; }
}

__global__ void k_count(const int* __restrict__ ei) {
    int e = blockIdx.x * blockDim.x + threadIdx.x;
    if (e >= EE) return;
    int s, d;
    if (g_is64) { s = ei[2 * (size_t)e]; d = ei[2 * ((size_t)EE + e)]; }
    else        { s = ei[e];             d = ei[(size_t)EE + e]; }
    // defensive clamp: a wrong dtype guess must never trap (it would fail rel-err instead)
    if ((unsigned)s >= NN) s = 0;
    if ((unsigned)d >= NN) d = 0;
    g_srci[e] = s;
    g_dsti[e] = d;
    atomicAdd(&g_degi[d], 1);
}

__global__ void k_scan() {   // exclusive prefix sum of g_degi -> g_ptr (1 block, 1024 thr)
    __shared__ int wsum[32];
    __shared__ int carry;
    int tid = threadIdx.x, lane = tid & 31, wid = tid >> 5;
    if (tid == 0) carry = 0;
    __syncthreads();
    for (int base = 0; base < NN; base += 1024) {
        int i = base + tid;
        int v = (i < NN) ? g_degi[i] : 0;
        int sc = v;
        #pragma unroll
        for (int o = 1; o < 32; o <<= 1) { int t = __shfl_up_sync(0xffffffffu, sc, o); if (lane >= o) sc += t; }
        if (lane == 31) wsum[wid] = sc;
        __syncthreads();
        if (wid == 0) {
            int ws = wsum[lane];
            #pragma unroll
            for (int o = 1; o < 32; o <<= 1) { int t = __shfl_up_sync(0xffffffffu, ws, o); if (lane >= o) ws += t; }
            wsum[lane] = ws;
        }
        __syncthreads();
        int excl = sc - v + (wid ? wsum[wid - 1] : 0) + carry;
        if (i < NN) g_ptr[i] = excl;
        __syncthreads();
        if (tid == 0) carry += wsum[31];
        __syncthreads();
    }
}

__global__ void k_fill() {
    int e = blockIdx.x * blockDim.x + threadIdx.x;
    if (e >= EE) return;
    int d = g_dsti[e];
    int pos = atomicAdd(&g_cursor[d], 1);
    g_csrc[g_ptr[d] + pos] = g_srci[e];
}

// ---------------- mean aggregation: one warp per node, writes [agg | root] row ----------------
__global__ void k_agg(const float* __restrict__ Xg, const float* __restrict__ Xr) {
    int t = blockIdx.x * blockDim.x + threadIdx.x;
    int node = t >> 5, lane = t & 31;
    if (node >= NN) return;
    int beg = g_ptr[node];
    int deg = g_degi[node];
    float4 acc = make_float4(0.f, 0.f, 0.f, 0.f);
    for (int j = 0; j < deg; j++) {
        int s = g_csrc[beg + j];
        float4 v = ((const float4*)(Xg + (size_t)s * FH))[lane];
        acc.x += v.x; acc.y += v.y; acc.z += v.z; acc.w += v.w;
    }
    float inv = 1.0f / (float)(deg > 1 ? deg : 1);
    float4* crow = (float4*)(g_cat + (size_t)node * 256);
    crow[lane]      = make_float4(acc.x * inv, acc.y * inv, acc.z * inv, acc.w * inv);
    crow[lane + 32] = ((const float4*)(Xr + (size_t)node * FH))[lane];
}

// ---------------- weight / bias packing ----------------
__global__ void k_pack2(const float* __restrict__ a, int na, const float* __restrict__ b, int nb) {
    int i = blockIdx.x * blockDim.x + threadIdx.x;
    if (i < na + nb) g_W[i] = (i < na) ? a[i] : b[i - na];
}

__global__ void k_packw3(const float* __restrict__ W3) {  // -> g_W[128][512]
    int i = blockIdx.x * blockDim.x + threadIdx.x;
    if (i >= 128 * 512) return;
    int k = i >> 9, j = i & 511;
    g_W[i] = (j < 256) ? W3[k * 256 + j] : W3[(128 + k) * 256 + (j - 256)];
}

__global__ void k_packbias(const float* __restrict__ b, int nb, int ntot) {
    int i = blockIdx.x * blockDim.x + threadIdx.x;
    if (i < ntot) g_bias[i] = (i < nb) ? b[i] : 0.f;
}

// ---------------- fp32 SGEMM: C[M,N] = op(A[M,K] @ g_W[K,N] + g_bias), tile 128x128, BK=8 ----------------
template<bool RELU>
__global__ void sgemm_kernel(const float* __restrict__ A, int M, int K, int lda,
                             int ldb, float* __restrict__ C, int ldc) {
    __shared__ float As[8][128];
    __shared__ float Bs[8][128];
    const int tid = threadIdx.x;            // 256
    const int bn = blockIdx.x * 128;
    const int bm = blockIdx.y * 128;
    const int tx = tid & 15, ty = tid >> 4;
    const int rowb = ty * 8, colb = tx * 8;
    const int arow = tid >> 1, acol = (tid & 1) * 4;
    const int brow = tid >> 5, bcol = (tid & 31) * 4;
    const bool arow_ok = (bm + arow) < M;

    float acc[8][8] = {};
    for (int k0 = 0; k0 < K; k0 += 8) {
        float4 av = make_float4(0.f, 0.f, 0.f, 0.f);
        if (arow_ok) av = *(const float4*)(A + (size_t)(bm + arow) * lda + k0 + acol);
        float4 bv = *(const float4*)(g_W + (size_t)(k0 + brow) * ldb + bn + bcol);
        __syncthreads();
        As[acol + 0][arow] = av.x; As[acol + 1][arow] = av.y;
        As[acol + 2][arow] = av.z; As[acol + 3][arow] = av.w;
        *(float4*)(&Bs[brow][bcol]) = bv;
        __syncthreads();
        #pragma unroll
        for (int kk = 0; kk < 8; kk++) {
            float a[8], b[8];
            #pragma unroll
            for (int i = 0; i < 8; i++) a[i] = As[kk][rowb + i];
            #pragma unroll
            for (int j = 0; j < 8; j++) b[j] = Bs[kk][colb + j];
            #pragma unroll
            for (int i = 0; i < 8; i++)
                #pragma unroll
                for (int j = 0; j < 8; j++)
                    acc[i][j] += a[i] * b[j];
        }
    }
    #pragma unroll
    for (int i = 0; i < 8; i++) {
        int r = bm + rowb + i;
        if (r >= M) break;
        #pragma unroll
        for (int j = 0; j < 8; j++) {
            float v = acc[i][j] + g_bias[bn + colb + j];
            if (RELU) v = fmaxf(v, 0.f);
            C[(size_t)r * ldc + bn + colb + j] = v;
        }
    }
}

// ---------------- per-edge prediction: warp per edge ----------------
__global__ void k_edge(const float* __restrict__ W4, const float* __restrict__ b4,
                       float* __restrict__ out) {
    __shared__ float4 w4s[64];
    int tid = threadIdx.x;
    if (tid < 64) w4s[tid] = ((const float4*)W4)[tid];
    __syncthreads();
    int gw = (blockIdx.x * blockDim.x + tid) >> 5;
    int lane = tid & 31;
    if (gw >= EE) return;
    int s = g_srci[gw], d = g_dsti[gw];
    const float4* Ar = (const float4*)(g_AB + (size_t)s * 512);
    const float4* Br = (const float4*)(g_AB + (size_t)d * 512 + 256);
    float acc = 0.f;
    #pragma unroll
    for (int i = 0; i < 2; i++) {
        float4 a = Ar[lane + 32 * i];
        float4 b = Br[lane + 32 * i];
        float4 w = w4s[lane + 32 * i];
        acc += fmaxf(a.x + b.x, 0.f) * w.x + fmaxf(a.y + b.y, 0.f) * w.y +
               fmaxf(a.z + b.z, 0.f) * w.z + fmaxf(a.w + b.w, 0.f) * w.w;
    }
    #pragma unroll
    for (int o = 16; o; o >>= 1) acc += __shfl_down_sync(0xffffffffu, acc, o);
    if (lane == 0) out[gw] = acc + b4[0];
}

// ---------------- launch ----------------
extern "C" void kernel_launch(void* const* d_in, const int* in_sizes, int n_in,
                              void* d_out, int out_size) {
    const float* x   = (const float*)d_in[0];
    const int*   ei  = (const int*)d_in[1];   // dtype sniffed at runtime (int32 vs int64)
    const float* W1l = (const float*)d_in[2];
    const float* b1l = (const float*)d_in[3];
    const float* W1r = (const float*)d_in[4];
    const float* W2l = (const float*)d_in[5];
    const float* b2l = (const float*)d_in[6];
    const float* W2r = (const float*)d_in[7];
    const float* W3  = (const float*)d_in[8];
    const float* b3  = (const float*)d_in[9];
    const float* W4  = (const float*)d_in[10];
    const float* b4  = (const float*)d_in[11];
    float* out = (float*)d_out;

    // Resolve REAL device addresses of __device__ globals for host-side kernel args.
    float *p_cat, *p_h1, *p_h2, *p_AB;
    cudaGetSymbolAddress((void**)&p_cat, g_cat);
    cudaGetSymbolAddress((void**)&p_h1,  g_h1);
    cudaGetSymbolAddress((void**)&p_h2,  g_h2);
    cudaGetSymbolAddress((void**)&p_AB,  g_AB);

    const int TB = 256;
    // CSR build
    k_detect<<<1, 256>>>(ei);
    k_init<<<(NN + TB - 1) / TB, TB>>>();
    k_count<<<(EE + TB - 1) / TB, TB>>>(ei);
    k_scan<<<1, 1024>>>();
    k_fill<<<(EE + TB - 1) / TB, TB>>>();

    const int aggGrid = (NN * 32 + TB - 1) / TB;
    const int mTiles  = (NN + 127) / 128;   // 391

    // SAGE layer 1: h1 = relu([mean_agg(x)|x] @ [W1l;W1r] + b1l)
    k_agg<<<aggGrid, TB>>>(x, x);
    k_pack2<<<(2 * 128 * 128 + TB - 1) / TB, TB>>>(W1l, 128 * 128, W1r, 128 * 128);
    k_packbias<<<1, 128>>>(b1l, 128, 128);
    sgemm_kernel<true><<<dim3(1, mTiles), 256>>>(p_cat, NN, 256, 256, 128, p_h1, 128);

    // SAGE layer 2
    k_agg<<<aggGrid, TB>>>(p_h1, p_h1);
    k_pack2<<<(2 * 128 * 128 + TB - 1) / TB, TB>>>(W2l, 128 * 128, W2r, 128 * 128);
    k_packbias<<<1, 128>>>(b2l, 128, 128);
    sgemm_kernel<true><<<dim3(1, mTiles), 256>>>(p_cat, NN, 256, 256, 128, p_h2, 128);

    // Edge-MLP factorization: AB[:,0:256] = h2@W3_top + b3, AB[:,256:512] = h2@W3_bot
    k_packw3<<<(128 * 512 + TB - 1) / TB, TB>>>(W3);
    k_packbias<<<(512 + TB - 1) / TB, TB>>>(b3, 256, 512);
    sgemm_kernel<false><<<dim3(4, mTiles), 256>>>(p_h2, NN, 128, 128, 512, p_AB, 512);

    // Per-edge: dot(relu(A[src]+B[dst]), W4) + b4
    k_edge<<<(EE * 32 + TB - 1) / TB, TB>>>(W4, b4, out);
}

// round 4
// speedup vs baseline: 1.7560x; 1.7560x over previous
#include <cuda_runtime.h>
#include <cuda_bf16.h>

#define NN 50000
#define EE 800000
#define FH 128
#define SCAN_B 256
#define NBLK ((NN + SCAN_B - 1) / SCAN_B)

// ---------------- scratch (device globals; no allocation allowed) ----------------
__device__ int   g_is64;
__device__ int   g_degi[NN];
__device__ int   g_ptr[NN];
__device__ int   g_cursor[NN];
__device__ int   g_bsum[NBLK];
__device__ int   g_boff[NBLK];
__device__ int   g_csrc[EE];
__device__ int   g_cdst[EE];
__device__ int   g_eid[EE];
__device__ int   g_srci[EE];
__device__ int   g_dsti[EE];
__device__ float g_cat[(size_t)NN * 256];   // [agg | root] input to SAGE gemms
__device__ float g_h1[(size_t)NN * 128];
__device__ float g_h2[(size_t)NN * 128];
__device__ float g_AB[(size_t)NN * 512];    // cols 0..255 = A(+b3), 256..511 = B
__device__ float g_W[256 * 512];            // packed weight buffer (reused per stage)
__device__ float g_bias[512];

// ---------------- edge_index dtype detection (int32 vs int64) ----------------
__global__ void k_detect(const int* __restrict__ ei_raw) {
    __shared__ int nz;
    if (threadIdx.x == 0) nz = 0;
    __syncthreads();
    for (int i = threadIdx.x; i < 1024; i += blockDim.x)
        if (ei_raw[2 * i + 1] != 0) nz = 1;
    __syncthreads();
    if (threadIdx.x == 0) g_is64 = (nz == 0) ? 1 : 0;
}

// ---------------- CSR construction ----------------
__global__ void k_init() {
    int i = blockIdx.x * blockDim.x + threadIdx.x;
    if (i < NN) { g_degi[i] = 0; g_cursor[i] = 0; }
}

__global__ void k_count(const int* __restrict__ ei) {
    int e = blockIdx.x * blockDim.x + threadIdx.x;
    if (e >= EE) return;
    int s, d;
    if (g_is64) { s = ei[2 * (size_t)e]; d = ei[2 * ((size_t)EE + e)]; }
    else        { s = ei[e];             d = ei[(size_t)EE + e]; }
    if ((unsigned)s >= NN) s = 0;
    if ((unsigned)d >= NN) d = 0;
    g_srci[e] = s;
    g_dsti[e] = d;
    atomicAdd(&g_degi[d], 1);
}

// 3-phase parallel exclusive scan of g_degi -> g_ptr
__global__ void k_bsum() {
    int b = blockIdx.x, t = threadIdx.x, i = b * SCAN_B + t;
    int v = (i < NN) ? g_degi[i] : 0;
    #pragma unroll
    for (int o = 16; o; o >>= 1) v += __shfl_down_sync(0xffffffffu, v, o);
    __shared__ int ws[8];
    if ((t & 31) == 0) ws[t >> 5] = v;
    __syncthreads();
    if (t < 8) {
        int s = ws[t];
        #pragma unroll
        for (int o = 4; o; o >>= 1) s += __shfl_down_sync(0xffu, s, o);
        if (t == 0) g_bsum[b] = s;
    }
}

__global__ void k_bscan() {   // 1 block, 256 thr: exclusive scan of NBLK block sums
    int t = threadIdx.x, lane = t & 31, w = t >> 5;
    int v = (t < NBLK) ? g_bsum[t] : 0;
    int sc = v;
    #pragma unroll
    for (int o = 1; o < 32; o <<= 1) { int x = __shfl_up_sync(0xffffffffu, sc, o); if (lane >= o) sc += x; }
    __shared__ int ws[8];
    if (lane == 31) ws[w] = sc;
    __syncthreads();
    int add = 0;
    for (int j = 0; j < w; j++) add += ws[j];
    if (t < NBLK) g_boff[t] = sc - v + add;
}

__global__ void k_scan2() {   // intra-block exclusive scan + block offset
    int b = blockIdx.x, t = threadIdx.x, i = b * SCAN_B + t;
    int lane = t & 31, w = t >> 5;
    int v = (i < NN) ? g_degi[i] : 0;
    int sc = v;
    #pragma unroll
    for (int o = 1; o < 32; o <<= 1) { int x = __shfl_up_sync(0xffffffffu, sc, o); if (lane >= o) sc += x; }
    __shared__ int ws[8];
    if (lane == 31) ws[w] = sc;
    __syncthreads();
    int add = 0;
    for (int j = 0; j < w; j++) add += ws[j];
    if (i < NN) g_ptr[i] = sc - v + add + g_boff[b];
}

__global__ void k_fill() {
    int e = blockIdx.x * blockDim.x + threadIdx.x;
    if (e >= EE) return;
    int d = g_dsti[e];
    int pos = g_ptr[d] + atomicAdd(&g_cursor[d], 1);
    g_csrc[pos] = g_srci[e];
    g_cdst[pos] = d;
    g_eid[pos]  = e;
}

// ---------------- mean aggregation: one warp per node, writes [agg | root] row ----------------
__global__ void k_agg(const float* __restrict__ Xg, const float* __restrict__ Xr) {
    int t = blockIdx.x * blockDim.x + threadIdx.x;
    int node = t >> 5, lane = t & 31;
    if (node >= NN) return;
    int beg = g_ptr[node];
    int deg = g_degi[node];
    float4 acc = make_float4(0.f, 0.f, 0.f, 0.f);
    for (int j = 0; j < deg; j++) {
        int s = g_csrc[beg + j];
        float4 v = ((const float4*)(Xg + (size_t)s * FH))[lane];
        acc.x += v.x; acc.y += v.y; acc.z += v.z; acc.w += v.w;
    }
    float inv = 1.0f / (float)(deg > 1 ? deg : 1);
    float4* crow = (float4*)(g_cat + (size_t)node * 256);
    crow[lane]      = make_float4(acc.x * inv, acc.y * inv, acc.z * inv, acc.w * inv);
    crow[lane + 32] = ((const float4*)(Xr + (size_t)node * FH))[lane];
}

// ---------------- weight / bias packing ----------------
__global__ void k_pack2(const float* __restrict__ a, int na, const float* __restrict__ b, int nb) {
    int i = blockIdx.x * blockDim.x + threadIdx.x;
    if (i < na + nb) g_W[i] = (i < na) ? a[i] : b[i - na];
}

__global__ void k_packw3(const float* __restrict__ W3) {  // -> g_W[128][512]
    int i = blockIdx.x * blockDim.x + threadIdx.x;
    if (i >= 128 * 512) return;
    int k = i >> 9, j = i & 511;
    g_W[i] = (j < 256) ? W3[k * 256 + j] : W3[(128 + k) * 256 + (j - 256)];
}

__global__ void k_packbias(const float* __restrict__ b, int nb, int ntot) {
    int i = blockIdx.x * blockDim.x + threadIdx.x;
    if (i < ntot) g_bias[i] = (i < nb) ? b[i] : 0.f;
}

// ---------------- tf32 tensor-core GEMM: C = op(A[M,K] @ g_W[K,N] + g_bias) ----------------
// tile 128(M) x 128(N), BK=16; 8 warps, each 32x64 via m16n8k8 mma.sync (fp32 accum)
__device__ __forceinline__ unsigned f2tf32(float f) {
    unsigned u;
    asm("cvt.rna.tf32.f32 %0, %1;" : "=r"(u) : "f"(f));
    return u;
}

template<bool RELU>
__global__ __launch_bounds__(256) void gemm_tf32(const float* __restrict__ A, int M, int K,
                                                 int ldb, float* __restrict__ C, int ldc) {
    __shared__ unsigned As[16][136];   // [k][m], pad 8 -> conflict-free frag loads
    __shared__ unsigned Bs[16][136];   // [k][n]
    const int tid = threadIdx.x;
    const int bm = blockIdx.y * 128;
    const int bn = blockIdx.x * 128;
    const int wid = tid >> 5, lane = tid & 31;
    const int warp_m = (wid & 3) * 32, warp_n = (wid >> 2) * 64;
    const int g = lane >> 2, q = lane & 3;

    float acc[2][8][4];
    #pragma unroll
    for (int i = 0; i < 2; i++)
        #pragma unroll
        for (int j = 0; j < 8; j++)
            #pragma unroll
            for (int r = 0; r < 4; r++) acc[i][j][r] = 0.f;

    const int lda = K;
    for (int k0 = 0; k0 < K; k0 += 16) {
        float4 av[2], bv[2];
        #pragma unroll
        for (int i = 0; i < 2; i++) {
            int f = tid + i * 256;
            int ar = f >> 2, ac4 = (f & 3) * 4;
            av[i] = make_float4(0.f, 0.f, 0.f, 0.f);
            if (bm + ar < M)
                av[i] = *(const float4*)(A + (size_t)(bm + ar) * lda + k0 + ac4);
            int br = f >> 5, bc4 = (f & 31) * 4;
            bv[i] = *(const float4*)(g_W + (size_t)(k0 + br) * ldb + bn + bc4);
        }
        __syncthreads();
        #pragma unroll
        for (int i = 0; i < 2; i++) {
            int f = tid + i * 256;
            int ar = f >> 2, ac4 = (f & 3) * 4;
            As[ac4 + 0][ar] = f2tf32(av[i].x);
            As[ac4 + 1][ar] = f2tf32(av[i].y);
            As[ac4 + 2][ar] = f2tf32(av[i].z);
            As[ac4 + 3][ar] = f2tf32(av[i].w);
            int br = f >> 5, bc4 = (f & 31) * 4;
            Bs[br][bc4 + 0] = f2tf32(bv[i].x);
            Bs[br][bc4 + 1] = f2tf32(bv[i].y);
            Bs[br][bc4 + 2] = f2tf32(bv[i].z);
            Bs[br][bc4 + 3] = f2tf32(bv[i].w);
        }
        __syncthreads();
        #pragma unroll
        for (int ks = 0; ks < 16; ks += 8) {
            unsigned a[2][4], b[8][2];
            #pragma unroll
            for (int mt = 0; mt < 2; mt++) {
                int r0 = warp_m + mt * 16 + g;
                a[mt][0] = As[ks + q][r0];
                a[mt][1] = As[ks + q][r0 + 8];
                a[mt][2] = As[ks + q + 4][r0];
                a[mt][3] = As[ks + q + 4][r0 + 8];
            }
            #pragma unroll
            for (int nt = 0; nt < 8; nt++) {
                int c = warp_n + nt * 8 + g;
                b[nt][0] = Bs[ks + q][c];
                b[nt][1] = Bs[ks + q + 4][c];
            }
            #pragma unroll
            for (int mt = 0; mt < 2; mt++)
                #pragma unroll
                for (int nt = 0; nt < 8; nt++) {
                    float* c = acc[mt][nt];
                    asm volatile(
                        "mma.sync.aligned.m16n8k8.row.col.f32.tf32.tf32.f32 "
                        "{%0,%1,%2,%3}, {%4,%5,%6,%7}, {%8,%9}, {%0,%1,%2,%3};\n"
                        : "+f"(c[0]), "+f"(c[1]), "+f"(c[2]), "+f"(c[3])
                        : "r"(a[mt][0]), "r"(a[mt][1]), "r"(a[mt][2]), "r"(a[mt][3]),
                          "r"(b[nt][0]), "r"(b[nt][1]));
                }
        }
    }
    // epilogue: bias + optional relu
    #pragma unroll
    for (int mt = 0; mt < 2; mt++) {
        int r0 = bm + warp_m + mt * 16 + g;
        #pragma unroll
        for (int nt = 0; nt < 8; nt++) {
            int c0 = bn + warp_n + nt * 8 + 2 * q;
            float bi0 = g_bias[c0], bi1 = g_bias[c0 + 1];
            if (r0 < M) {
                float v0 = acc[mt][nt][0] + bi0, v1 = acc[mt][nt][1] + bi1;
                if (RELU) { v0 = fmaxf(v0, 0.f); v1 = fmaxf(v1, 0.f); }
                *(float2*)(C + (size_t)r0 * ldc + c0) = make_float2(v0, v1);
            }
            if (r0 + 8 < M) {
                float v2 = acc[mt][nt][2] + bi0, v3 = acc[mt][nt][3] + bi1;
                if (RELU) { v2 = fmaxf(v2, 0.f); v3 = fmaxf(v3, 0.f); }
                *(float2*)(C + (size_t)(r0 + 8) * ldc + c0) = make_float2(v2, v3);
            }
        }
    }
}

// ---------------- per-edge prediction: warp per CSR slot (dst-grouped for locality) ----------------
__global__ void k_edge(const float* __restrict__ W4, const float* __restrict__ b4,
                       float* __restrict__ out) {
    __shared__ float4 w4s[64];
    int tid = threadIdx.x;
    if (tid < 64) w4s[tid] = ((const float4*)W4)[tid];
    __syncthreads();
    int p = (blockIdx.x * blockDim.x + tid) >> 5;
    int lane = tid & 31;
    if (p >= EE) return;
    int s = g_csrc[p], d = g_cdst[p];
    const float4* Ar = (const float4*)(g_AB + (size_t)s * 512);
    const float4* Br = (const float4*)(g_AB + (size_t)d * 512 + 256);
    float acc = 0.f;
    #pragma unroll
    for (int i = 0; i < 2; i++) {
        float4 a = Ar[lane + 32 * i];
        float4 b = Br[lane + 32 * i];
        float4 w = w4s[lane + 32 * i];
        acc += fmaxf(a.x + b.x, 0.f) * w.x + fmaxf(a.y + b.y, 0.f) * w.y +
               fmaxf(a.z + b.z, 0.f) * w.z + fmaxf(a.w + b.w, 0.f) * w.w;
    }
    #pragma unroll
    for (int o = 16; o; o >>= 1) acc += __shfl_down_sync(0xffffffffu, acc, o);
    if (lane == 0) out[g_eid[p]] = acc + b4[0];
}

// ---------------- launch ----------------
extern "C" void kernel_launch(void* const* d_in, const int* in_sizes, int n_in,
                              void* d_out, int out_size) {
    const float* x   = (const float*)d_in[0];
    const int*   ei  = (const int*)d_in[1];   // dtype sniffed at runtime (int32 vs int64)
    const float* W1l = (const float*)d_in[2];
    const float* b1l = (const float*)d_in[3];
    const float* W1r = (const float*)d_in[4];
    const float* W2l = (const float*)d_in[5];
    const float* b2l = (const float*)d_in[6];
    const float* W2r = (const float*)d_in[7];
    const float* W3  = (const float*)d_in[8];
    const float* b3  = (const float*)d_in[9];
    const float* W4  = (const float*)d_in[10];
    const float* b4  = (const float*)d_in[11];
    float* out = (float*)d_out;

    float *p_cat, *p_h1, *p_h2, *p_AB;
    cudaGetSymbolAddress((void**)&p_cat, g_cat);
    cudaGetSymbolAddress((void**)&p_h1,  g_h1);
    cudaGetSymbolAddress((void**)&p_h2,  g_h2);
    cudaGetSymbolAddress((void**)&p_AB,  g_AB);

    const int TB = 256;
    // CSR build
    k_detect<<<1, 256>>>(ei);
    k_init<<<(NN + TB - 1) / TB, TB>>>();
    k_count<<<(EE + TB - 1) / TB, TB>>>(ei);
    k_bsum<<<NBLK, SCAN_B>>>();
    k_bscan<<<1, 256>>>();
    k_scan2<<<NBLK, SCAN_B>>>();
    k_fill<<<(EE + TB - 1) / TB, TB>>>();

    const int aggGrid = (NN * 32 + TB - 1) / TB;
    const int mTiles  = (NN + 127) / 128;   // 391

    // SAGE layer 1: h1 = relu([mean_agg(x)|x] @ [W1l;W1r] + b1l)
    k_agg<<<aggGrid, TB>>>(x, x);
    k_pack2<<<(2 * 128 * 128 + TB - 1) / TB, TB>>>(W1l, 128 * 128, W1r, 128 * 128);
    k_packbias<<<1, 128>>>(b1l, 128, 128);
    gemm_tf32<true><<<dim3(1, mTiles), 256>>>(p_cat, NN, 256, 128, p_h1, 128);

    // SAGE layer 2
    k_agg<<<aggGrid, TB>>>(p_h1, p_h1);
    k_pack2<<<(2 * 128 * 128 + TB - 1) / TB, TB>>>(W2l, 128 * 128, W2r, 128 * 128);
    k_packbias<<<1, 128>>>(b2l, 128, 128);
    gemm_tf32<true><<<dim3(1, mTiles), 256>>>(p_cat, NN, 256, 128, p_h2, 128);

    // Edge-MLP factorization: AB[:,0:256] = h2@W3_top + b3, AB[:,256:512] = h2@W3_bot
    k_packw3<<<(128 * 512 + TB - 1) / TB, TB>>>(W3);
    k_packbias<<<(512 + TB - 1) / TB, TB>>>(b3, 256, 512);
    gemm_tf32<false><<<dim3(4, mTiles), 256>>>(p_h2, NN, 128, 512, p_AB, 512);

    // Per-edge: dot(relu(A[src]+B[dst]), W4) + b4 (dst-grouped CSR order)
    k_edge<<<(EE * 32 + TB - 1) / TB, TB>>>(W4, b4, out);
}

// round 5
// speedup vs baseline: 2.3060x; 1.3132x over previous
#include <cuda_runtime.h>
#include <cuda_fp16.h>

#define NN 50000
#define EE 800000
#define FH 128
#define SCAN_B 256
#define NBLK ((NN + SCAN_B - 1) / SCAN_B)
#define EPW 8   // edges per warp in k_edge

// ---------------- scratch (device globals; no allocation allowed) ----------------
__device__ int    g_is64;
__device__ int    g_degi[NN];
__device__ int    g_ptr[NN];
__device__ int    g_cursor[NN];
__device__ int    g_bsum[NBLK];
__device__ int    g_boff[NBLK];
__device__ int2   g_e2[EE];                  // CSR slot: {src | dst<<16, eid}
__device__ int    g_srci[EE];
__device__ int    g_dsti[EE];
__device__ float  g_cat[(size_t)NN * 256];   // [agg | root] input to SAGE gemms
__device__ float  g_h1[(size_t)NN * 128];
__device__ float  g_h2[(size_t)NN * 128];
__device__ __half g_ABh[(size_t)NN * 512];   // fp16: cols 0..255 = A(+b3), 256..511 = B
__device__ float  g_W[256 * 512];            // packed weight buffer (reused per stage)
__device__ float  g_bias[512];

// ---------------- edge_index dtype detection (int32 vs int64) ----------------
__global__ void k_detect(const int* __restrict__ ei_raw) {
    __shared__ int nz;
    if (threadIdx.x == 0) nz = 0;
    __syncthreads();
    for (int i = threadIdx.x; i < 1024; i += blockDim.x)
        if (ei_raw[2 * i + 1] != 0) nz = 1;
    __syncthreads();
    if (threadIdx.x == 0) g_is64 = (nz == 0) ? 1 : 0;
}

// ---------------- CSR construction ----------------
__global__ void k_init() {
    int i = blockIdx.x * blockDim.x + threadIdx.x;
    if (i < NN) { g_degi[i] = 0; g_cursor[i] = 0; }
}

__global__ void k_count(const int* __restrict__ ei) {
    int e = blockIdx.x * blockDim.x + threadIdx.x;
    if (e >= EE) return;
    int s, d;
    if (g_is64) { s = ei[2 * (size_t)e]; d = ei[2 * ((size_t)EE + e)]; }
    else        { s = ei[e];             d = ei[(size_t)EE + e]; }
    if ((unsigned)s >= NN) s = 0;
    if ((unsigned)d >= NN) d = 0;
    g_srci[e] = s;
    g_dsti[e] = d;
    atomicAdd(&g_degi[d], 1);
}

// 3-phase parallel exclusive scan of g_degi -> g_ptr
__global__ void k_bsum() {
    int b = blockIdx.x, t = threadIdx.x, i = b * SCAN_B + t;
    int v = (i < NN) ? g_degi[i] : 0;
    #pragma unroll
    for (int o = 16; o; o >>= 1) v += __shfl_down_sync(0xffffffffu, v, o);
    __shared__ int ws[8];
    if ((t & 31) == 0) ws[t >> 5] = v;
    __syncthreads();
    if (t < 8) {
        int s = ws[t];
        #pragma unroll
        for (int o = 4; o; o >>= 1) s += __shfl_down_sync(0xffu, s, o);
        if (t == 0) g_bsum[b] = s;
    }
}

__global__ void k_bscan() {
    int t = threadIdx.x, lane = t & 31, w = t >> 5;
    int v = (t < NBLK) ? g_bsum[t] : 0;
    int sc = v;
    #pragma unroll
    for (int o = 1; o < 32; o <<= 1) { int x = __shfl_up_sync(0xffffffffu, sc, o); if (lane >= o) sc += x; }
    __shared__ int ws[8];
    if (lane == 31) ws[w] = sc;
    __syncthreads();
    int add = 0;
    for (int j = 0; j < w; j++) add += ws[j];
    if (t < NBLK) g_boff[t] = sc - v + add;
}

__global__ void k_scan2() {
    int b = blockIdx.x, t = threadIdx.x, i = b * SCAN_B + t;
    int lane = t & 31, w = t >> 5;
    int v = (i < NN) ? g_degi[i] : 0;
    int sc = v;
    #pragma unroll
    for (int o = 1; o < 32; o <<= 1) { int x = __shfl_up_sync(0xffffffffu, sc, o); if (lane >= o) sc += x; }
    __shared__ int ws[8];
    if (lane == 31) ws[w] = sc;
    __syncthreads();
    int add = 0;
    for (int j = 0; j < w; j++) add += ws[j];
    if (i < NN) g_ptr[i] = sc - v + add + g_boff[b];
}

__global__ void k_fill() {
    int e = blockIdx.x * blockDim.x + threadIdx.x;
    if (e >= EE) return;
    int s = g_srci[e], d = g_dsti[e];
    int pos = g_ptr[d] + atomicAdd(&g_cursor[d], 1);
    g_e2[pos] = make_int2(s | (d << 16), e);
}

// ---------------- mean aggregation: one warp per node, writes [agg | root] row ----------------
__global__ void k_agg(const float* __restrict__ Xg, const float* __restrict__ Xr) {
    int t = blockIdx.x * blockDim.x + threadIdx.x;
    int node = t >> 5, lane = t & 31;
    if (node >= NN) return;
    int beg = g_ptr[node];
    int deg = g_degi[node];
    float4 acc = make_float4(0.f, 0.f, 0.f, 0.f);
    for (int j = 0; j < deg; j++) {
        int s = g_e2[beg + j].x & 0xffff;
        float4 v = ((const float4*)(Xg + (size_t)s * FH))[lane];
        acc.x += v.x; acc.y += v.y; acc.z += v.z; acc.w += v.w;
    }
    float inv = 1.0f / (float)(deg > 1 ? deg : 1);
    float4* crow = (float4*)(g_cat + (size_t)node * 256);
    crow[lane]      = make_float4(acc.x * inv, acc.y * inv, acc.z * inv, acc.w * inv);
    crow[lane + 32] = ((const float4*)(Xr + (size_t)node * FH))[lane];
}

// ---------------- weight / bias packing ----------------
__global__ void k_pack2(const float* __restrict__ a, int na, const float* __restrict__ b, int nb) {
    int i = blockIdx.x * blockDim.x + threadIdx.x;
    if (i < na + nb) g_W[i] = (i < na) ? a[i] : b[i - na];
}

__global__ void k_packw3(const float* __restrict__ W3) {  // -> g_W[128][512]
    int i = blockIdx.x * blockDim.x + threadIdx.x;
    if (i >= 128 * 512) return;
    int k = i >> 9, j = i & 511;
    g_W[i] = (j < 256) ? W3[k * 256 + j] : W3[(128 + k) * 256 + (j - 256)];
}

__global__ void k_packbias(const float* __restrict__ b, int nb, int ntot) {
    int i = blockIdx.x * blockDim.x + threadIdx.x;
    if (i < ntot) g_bias[i] = (i < nb) ? b[i] : 0.f;
}

// ---------------- tf32 tensor-core GEMM: C = op(A[M,K] @ g_W[K,N] + g_bias) ----------------
__device__ __forceinline__ unsigned f2tf32(float f) {
    unsigned u;
    asm("cvt.rna.tf32.f32 %0, %1;" : "=r"(u) : "f"(f));
    return u;
}

template<bool RELU, bool HALF_OUT>
__global__ __launch_bounds__(256) void gemm_tf32(const float* __restrict__ A, int M, int K,
                                                 int ldb, void* __restrict__ Cv, int ldc) {
    __shared__ unsigned As[16][136];   // [k][m], pad 8 -> conflict-free frag loads
    __shared__ unsigned Bs[16][136];   // [k][n]
    const int tid = threadIdx.x;
    const int bm = blockIdx.y * 128;
    const int bn = blockIdx.x * 128;
    const int wid = tid >> 5, lane = tid & 31;
    const int warp_m = (wid & 3) * 32, warp_n = (wid >> 2) * 64;
    const int g = lane >> 2, q = lane & 3;

    float acc[2][8][4];
    #pragma unroll
    for (int i = 0; i < 2; i++)
        #pragma unroll
        for (int j = 0; j < 8; j++)
            #pragma unroll
            for (int r = 0; r < 4; r++) acc[i][j][r] = 0.f;

    const int lda = K;
    for (int k0 = 0; k0 < K; k0 += 16) {
        float4 av[2], bv[2];
        #pragma unroll
        for (int i = 0; i < 2; i++) {
            int f = tid + i * 256;
            int ar = f >> 2, ac4 = (f & 3) * 4;
            av[i] = make_float4(0.f, 0.f, 0.f, 0.f);
            if (bm + ar < M)
                av[i] = *(const float4*)(A + (size_t)(bm + ar) * lda + k0 + ac4);
            int br = f >> 5, bc4 = (f & 31) * 4;
            bv[i] = *(const float4*)(g_W + (size_t)(k0 + br) * ldb + bn + bc4);
        }
        __syncthreads();
        #pragma unroll
        for (int i = 0; i < 2; i++) {
            int f = tid + i * 256;
            int ar = f >> 2, ac4 = (f & 3) * 4;
            As[ac4 + 0][ar] = f2tf32(av[i].x);
            As[ac4 + 1][ar] = f2tf32(av[i].y);
            As[ac4 + 2][ar] = f2tf32(av[i].z);
            As[ac4 + 3][ar] = f2tf32(av[i].w);
            int br = f >> 5, bc4 = (f & 31) * 4;
            Bs[br][bc4 + 0] = f2tf32(bv[i].x);
            Bs[br][bc4 + 1] = f2tf32(bv[i].y);
            Bs[br][bc4 + 2] = f2tf32(bv[i].z);
            Bs[br][bc4 + 3] = f2tf32(bv[i].w);
        }
        __syncthreads();
        #pragma unroll
        for (int ks = 0; ks < 16; ks += 8) {
            unsigned a[2][4], b[8][2];
            #pragma unroll
            for (int mt = 0; mt < 2; mt++) {
                int r0 = warp_m + mt * 16 + g;
                a[mt][0] = As[ks + q][r0];
                a[mt][1] = As[ks + q][r0 + 8];
                a[mt][2] = As[ks + q + 4][r0];
                a[mt][3] = As[ks + q + 4][r0 + 8];
            }
            #pragma unroll
            for (int nt = 0; nt < 8; nt++) {
                int c = warp_n + nt * 8 + g;
                b[nt][0] = Bs[ks + q][c];
                b[nt][1] = Bs[ks + q + 4][c];
            }
            #pragma unroll
            for (int mt = 0; mt < 2; mt++)
                #pragma unroll
                for (int nt = 0; nt < 8; nt++) {
                    float* c = acc[mt][nt];
                    asm volatile(
                        "mma.sync.aligned.m16n8k8.row.col.f32.tf32.tf32.f32 "
                        "{%0,%1,%2,%3}, {%4,%5,%6,%7}, {%8,%9}, {%0,%1,%2,%3};\n"
                        : "+f"(c[0]), "+f"(c[1]), "+f"(c[2]), "+f"(c[3])
                        : "r"(a[mt][0]), "r"(a[mt][1]), "r"(a[mt][2]), "r"(a[mt][3]),
                          "r"(b[nt][0]), "r"(b[nt][1]));
                }
        }
    }
    // epilogue: bias + optional relu, fp32 or fp16 output
    #pragma unroll
    for (int mt = 0; mt < 2; mt++) {
        int r0 = bm + warp_m + mt * 16 + g;
        #pragma unroll
        for (int nt = 0; nt < 8; nt++) {
            int c0 = bn + warp_n + nt * 8 + 2 * q;
            float bi0 = g_bias[c0], bi1 = g_bias[c0 + 1];
            if (r0 < M) {
                float v0 = acc[mt][nt][0] + bi0, v1 = acc[mt][nt][1] + bi1;
                if (RELU) { v0 = fmaxf(v0, 0.f); v1 = fmaxf(v1, 0.f); }
                if (HALF_OUT)
                    *(__half2*)((__half*)Cv + (size_t)r0 * ldc + c0) = __floats2half2_rn(v0, v1);
                else
                    *(float2*)((float*)Cv + (size_t)r0 * ldc + c0) = make_float2(v0, v1);
            }
            if (r0 + 8 < M) {
                float v2 = acc[mt][nt][2] + bi0, v3 = acc[mt][nt][3] + bi1;
                if (RELU) { v2 = fmaxf(v2, 0.f); v3 = fmaxf(v3, 0.f); }
                if (HALF_OUT)
                    *(__half2*)((__half*)Cv + (size_t)(r0 + 8) * ldc + c0) = __floats2half2_rn(v2, v3);
                else
                    *(float2*)((float*)Cv + (size_t)(r0 + 8) * ldc + c0) = make_float2(v2, v3);
            }
        }
    }
}

// ---------------- per-edge prediction: warp handles EPW edges, W4 in registers ----------------
__global__ void k_edge(const float* __restrict__ W4, const float* __restrict__ b4,
                       float* __restrict__ out) {
    int tid = threadIdx.x, lane = tid & 31;
    int warp = (blockIdx.x * blockDim.x + tid) >> 5;
    // lane owns output cols [lane*8, lane*8+8)
    float4 w0 = ((const float4*)W4)[lane * 2];
    float4 w1 = ((const float4*)W4)[lane * 2 + 1];
    float bb = b4[0];
    const __half2 hz = __floats2half2_rn(0.f, 0.f);
    int base = warp * EPW;
    #pragma unroll
    for (int i = 0; i < EPW; i++) {
        int p = base + i;
        if (p >= EE) return;
        int2 v = g_e2[p];
        int s = v.x & 0xffff;
        int d = (int)(((unsigned)v.x) >> 16);
        const uint4* Ar = (const uint4*)(g_ABh + (size_t)s * 512);
        const uint4* Br = (const uint4*)(g_ABh + (size_t)d * 512 + 256);
        uint4 a = Ar[lane];
        uint4 b = Br[lane];
        __half2 t0 = __hmax2(__hadd2(*(__half2*)&a.x, *(__half2*)&b.x), hz);
        __half2 t1 = __hmax2(__hadd2(*(__half2*)&a.y, *(__half2*)&b.y), hz);
        __half2 t2 = __hmax2(__hadd2(*(__half2*)&a.z, *(__half2*)&b.z), hz);
        __half2 t3 = __hmax2(__hadd2(*(__half2*)&a.w, *(__half2*)&b.w), hz);
        float2 f0 = __half22float2(t0), f1 = __half22float2(t1);
        float2 f2 = __half22float2(t2), f3 = __half22float2(t3);
        float acc = f0.x * w0.x + f0.y * w0.y + f1.x * w0.z + f1.y * w0.w +
                    f2.x * w1.x + f2.y * w1.y + f3.x * w1.z + f3.y * w1.w;
        #pragma unroll
        for (int o = 16; o; o >>= 1) acc += __shfl_down_sync(0xffffffffu, acc, o);
        if (lane == 0) out[v.y] = acc + bb;
    }
}

// ---------------- launch ----------------
extern "C" void kernel_launch(void* const* d_in, const int* in_sizes, int n_in,
                              void* d_out, int out_size) {
    const float* x   = (const float*)d_in[0];
    const int*   ei  = (const int*)d_in[1];   // dtype sniffed at runtime (int32 vs int64)
    const float* W1l = (const float*)d_in[2];
    const float* b1l = (const float*)d_in[3];
    const float* W1r = (const float*)d_in[4];
    const float* W2l = (const float*)d_in[5];
    const float* b2l = (const float*)d_in[6];
    const float* W2r = (const float*)d_in[7];
    const float* W3  = (const float*)d_in[8];
    const float* b3  = (const float*)d_in[9];
    const float* W4  = (const float*)d_in[10];
    const float* b4  = (const float*)d_in[11];
    float* out = (float*)d_out;

    float *p_cat, *p_h1, *p_h2;
    void  *p_ABh;
    cudaGetSymbolAddress((void**)&p_cat, g_cat);
    cudaGetSymbolAddress((void**)&p_h1,  g_h1);
    cudaGetSymbolAddress((void**)&p_h2,  g_h2);
    cudaGetSymbolAddress(&p_ABh, g_ABh);

    const int TB = 256;
    // CSR build
    k_detect<<<1, 256>>>(ei);
    k_init<<<(NN + TB - 1) / TB, TB>>>();
    k_count<<<(EE + TB - 1) / TB, TB>>>(ei);
    k_bsum<<<NBLK, SCAN_B>>>();
    k_bscan<<<1, 256>>>();
    k_scan2<<<NBLK, SCAN_B>>>();
    k_fill<<<(EE + TB - 1) / TB, TB>>>();

    const int aggGrid = (NN * 32 + TB - 1) / TB;
    const int mTiles  = (NN + 127) / 128;   // 391

    // SAGE layer 1: h1 = relu([mean_agg(x)|x] @ [W1l;W1r] + b1l)
    k_agg<<<aggGrid, TB>>>(x, x);
    k_pack2<<<(2 * 128 * 128 + TB - 1) / TB, TB>>>(W1l, 128 * 128, W1r, 128 * 128);
    k_packbias<<<1, 128>>>(b1l, 128, 128);
    gemm_tf32<true, false><<<dim3(1, mTiles), 256>>>(p_cat, NN, 256, 128, p_h1, 128);

    // SAGE layer 2
    k_agg<<<aggGrid, TB>>>(p_h1, p_h1);
    k_pack2<<<(2 * 128 * 128 + TB - 1) / TB, TB>>>(W2l, 128 * 128, W2r, 128 * 128);
    k_packbias<<<1, 128>>>(b2l, 128, 128);
    gemm_tf32<true, false><<<dim3(1, mTiles), 256>>>(p_cat, NN, 256, 128, p_h2, 128);

    // Edge-MLP factorization: ABh[:,0:256] = h2@W3_top + b3, ABh[:,256:512] = h2@W3_bot (fp16 out)
    k_packw3<<<(128 * 512 + TB - 1) / TB, TB>>>(W3);
    k_packbias<<<(512 + TB - 1) / TB, TB>>>(b3, 256, 512);
    gemm_tf32<false, true><<<dim3(4, mTiles), 256>>>(p_h2, NN, 128, 512, p_ABh, 512);

    // Per-edge: dot(relu(A[src]+B[dst]), W4) + b4 (dst-grouped CSR order, EPW edges/warp)
    const int edgeWarps = (EE + EPW - 1) / EPW;
    k_edge<<<(edgeWarps * 32 + TB - 1) / TB, TB>>>(W4, b4, out);
}

// round 6
// speedup vs baseline: 2.9939x; 1.2983x over previous
#include <cuda_runtime.h>
#include <cuda_fp16.h>

#define NN 50000
#define EE 800000
#define FH 128
#define SCAN_B 256
#define NBLK ((NN + SCAN_B - 1) / SCAN_B)
#define EPW 8   // edges per warp in k_edge

// ---------------- scratch (device globals; no allocation allowed) ----------------
__device__ int    g_is64;
__device__ int    g_degi[NN];
__device__ int    g_ptr[NN];
__device__ int    g_cursor[NN];
__device__ int    g_bsum[NBLK];
__device__ int    g_boff[NBLK];
__device__ int2   g_e2[EE];                   // CSR slot: {src | dst<<16, eid}
__device__ int    g_srci[EE];
__device__ int    g_dsti[EE];
__device__ __half g_xh[(size_t)NN * 128];     // x in fp16
__device__ __half g_cath[(size_t)NN * 256];   // [agg | root] fp16, GEMM input
__device__ __half g_h1h[(size_t)NN * 128];
__device__ __half g_h2h[(size_t)NN * 128];
__device__ __half g_ABh[(size_t)NN * 512];    // cols 0..255 = A(+b3), 256..511 = B
__device__ __half g_Wh[512 * 256];            // packed weights, n-major: [N][K]
__device__ float  g_bias[512];

// ---------------- edge_index dtype detection (int32 vs int64) ----------------
__global__ void k_detect(const int* __restrict__ ei_raw) {
    __shared__ int nz;
    if (threadIdx.x == 0) nz = 0;
    __syncthreads();
    for (int i = threadIdx.x; i < 1024; i += blockDim.x)
        if (ei_raw[2 * i + 1] != 0) nz = 1;
    __syncthreads();
    if (threadIdx.x == 0) g_is64 = (nz == 0) ? 1 : 0;
}

// ---------------- CSR construction ----------------
__global__ void k_init() {
    int i = blockIdx.x * blockDim.x + threadIdx.x;
    if (i < NN) { g_degi[i] = 0; g_cursor[i] = 0; }
}

__global__ void k_count(const int* __restrict__ ei) {
    int e = blockIdx.x * blockDim.x + threadIdx.x;
    if (e >= EE) return;
    int s, d;
    if (g_is64) { s = ei[2 * (size_t)e]; d = ei[2 * ((size_t)EE + e)]; }
    else        { s = ei[e];             d = ei[(size_t)EE + e]; }
    if ((unsigned)s >= NN) s = 0;
    if ((unsigned)d >= NN) d = 0;
    g_srci[e] = s;
    g_dsti[e] = d;
    atomicAdd(&g_degi[d], 1);
}

// 3-phase parallel exclusive scan of g_degi -> g_ptr
__global__ void k_bsum() {
    int b = blockIdx.x, t = threadIdx.x, i = b * SCAN_B + t;
    int v = (i < NN) ? g_degi[i] : 0;
    #pragma unroll
    for (int o = 16; o; o >>= 1) v += __shfl_down_sync(0xffffffffu, v, o);
    __shared__ int ws[8];
    if ((t & 31) == 0) ws[t >> 5] = v;
    __syncthreads();
    if (t < 8) {
        int s = ws[t];
        #pragma unroll
        for (int o = 4; o; o >>= 1) s += __shfl_down_sync(0xffu, s, o);
        if (t == 0) g_bsum[b] = s;
    }
}

__global__ void k_bscan() {
    int t = threadIdx.x, lane = t & 31, w = t >> 5;
    int v = (t < NBLK) ? g_bsum[t] : 0;
    int sc = v;
    #pragma unroll
    for (int o = 1; o < 32; o <<= 1) { int x = __shfl_up_sync(0xffffffffu, sc, o); if (lane >= o) sc += x; }
    __shared__ int ws[8];
    if (lane == 31) ws[w] = sc;
    __syncthreads();
    int add = 0;
    for (int j = 0; j < w; j++) add += ws[j];
    if (t < NBLK) g_boff[t] = sc - v + add;
}

__global__ void k_scan2() {
    int b = blockIdx.x, t = threadIdx.x, i = b * SCAN_B + t;
    int lane = t & 31, w = t >> 5;
    int v = (i < NN) ? g_degi[i] : 0;
    int sc = v;
    #pragma unroll
    for (int o = 1; o < 32; o <<= 1) { int x = __shfl_up_sync(0xffffffffu, sc, o); if (lane >= o) sc += x; }
    __shared__ int ws[8];
    if (lane == 31) ws[w] = sc;
    __syncthreads();
    int add = 0;
    for (int j = 0; j < w; j++) add += ws[j];
    if (i < NN) g_ptr[i] = sc - v + add + g_boff[b];
}

__global__ void k_fill() {
    int e = blockIdx.x * blockDim.x + threadIdx.x;
    if (e >= EE) return;
    int s = g_srci[e], d = g_dsti[e];
    int pos = g_ptr[d] + atomicAdd(&g_cursor[d], 1);
    g_e2[pos] = make_int2(s | (d << 16), e);
}

// ---------------- x -> fp16 ----------------
__global__ void k_half(const float* __restrict__ X) {
    size_t i = (size_t)(blockIdx.x * blockDim.x + threadIdx.x) * 8;
    if (i >= (size_t)NN * 128) return;
    float4 a = *(const float4*)(X + i);
    float4 b = *(const float4*)(X + i + 4);
    __half2 h0 = __floats2half2_rn(a.x, a.y), h1 = __floats2half2_rn(a.z, a.w);
    __half2 h2 = __floats2half2_rn(b.x, b.y), h3 = __floats2half2_rn(b.z, b.w);
    uint4 o;
    o.x = *(unsigned*)&h0; o.y = *(unsigned*)&h1; o.z = *(unsigned*)&h2; o.w = *(unsigned*)&h3;
    *(uint4*)(g_xh + i) = o;
}

// ---------------- mean aggregation (fp16 in, fp32 acc, fp16 out): warp per node ----------------
__global__ void k_agg(const __half* __restrict__ Xg, const __half* __restrict__ Xr) {
    int t = blockIdx.x * blockDim.x + threadIdx.x;
    int node = t >> 5, lane = t & 31;
    if (node >= NN) return;
    int beg = g_ptr[node];
    int deg = g_degi[node];
    float a0 = 0.f, a1 = 0.f, a2 = 0.f, a3 = 0.f;
    for (int j = 0; j < deg; j++) {
        int s = g_e2[beg + j].x & 0xffff;
        uint2 v = ((const uint2*)(Xg + (size_t)s * FH))[lane];   // 4 halves
        float2 f0 = __half22float2(*(__half2*)&v.x);
        float2 f1 = __half22float2(*(__half2*)&v.y);
        a0 += f0.x; a1 += f0.y; a2 += f1.x; a3 += f1.y;
    }
    float inv = 1.0f / (float)(deg > 1 ? deg : 1);
    __half2 o0 = __floats2half2_rn(a0 * inv, a1 * inv);
    __half2 o1 = __floats2half2_rn(a2 * inv, a3 * inv);
    uint2 pack; pack.x = *(unsigned*)&o0; pack.y = *(unsigned*)&o1;
    ((uint2*)(g_cath + (size_t)node * 256))[lane] = pack;                       // agg half
    ((uint2*)(g_cath + (size_t)node * 256 + 128))[lane] =
        ((const uint2*)(Xr + (size_t)node * FH))[lane];                         // root half
}

// ---------------- weight packing: fp32 [K][N] pair -> fp16 n-major [N][K] ----------------
__global__ void k_pack2h(const float* __restrict__ Wl, const float* __restrict__ Wr) {
    int i = blockIdx.x * blockDim.x + threadIdx.x;     // over 128*256
    if (i >= 128 * 256) return;
    int n = i >> 8, k = i & 255;
    float v = (k < 128) ? Wl[k * 128 + n] : Wr[(k - 128) * 128 + n];
    g_Wh[n * 256 + k] = __float2half_rn(v);
}

__global__ void k_packw3h(const float* __restrict__ W3) {   // -> g_Wh [512][128]
    int i = blockIdx.x * blockDim.x + threadIdx.x;     // over 512*128
    if (i >= 512 * 128) return;
    int n = i >> 7, k = i & 127;
    float v = (n < 256) ? W3[k * 256 + n] : W3[(128 + k) * 256 + (n - 256)];
    g_Wh[n * 128 + k] = __float2half_rn(v);
}

__global__ void k_packbias(const float* __restrict__ b, int nb, int ntot) {
    int i = blockIdx.x * blockDim.x + threadIdx.x;
    if (i < ntot) g_bias[i] = (i < nb) ? b[i] : 0.f;
}

// ---------------- fp16 tensor-core GEMM: C = op(A[M,K] @ Wh^T + bias), fp32 accum ----------------
// tile 128(M) x 128(N), BK=32; 8 warps, each 32x64 via m16n8k16; A,B smem [row][k] pad->40 halves
template<bool RELU>
__global__ __launch_bounds__(256) void gemm_h(const __half* __restrict__ A, int M, int K,
                                              __half* __restrict__ C, int ldc) {
    __shared__ __align__(16) __half As[128][40];
    __shared__ __align__(16) __half Bs[128][40];
    const int tid = threadIdx.x;
    const int bm = blockIdx.y * 128;
    const int bn = blockIdx.x * 128;
    const int wid = tid >> 5, lane = tid & 31;
    const int warp_m = (wid & 3) * 32, warp_n = (wid >> 2) * 64;
    const int g = lane >> 2, q = lane & 3;

    float acc[2][8][4];
    #pragma unroll
    for (int i = 0; i < 2; i++)
        #pragma unroll
        for (int j = 0; j < 8; j++)
            #pragma unroll
            for (int r = 0; r < 4; r++) acc[i][j][r] = 0.f;

    for (int k0 = 0; k0 < K; k0 += 32) {
        uint4 av[2], bv[2];
        #pragma unroll
        for (int i = 0; i < 2; i++) {
            int f = tid + i * 256;               // 0..511
            int r = f >> 2, c = (f & 3) * 8;     // 8 halves per uint4
            av[i] = make_uint4(0, 0, 0, 0);
            if (bm + r < M)
                av[i] = *(const uint4*)(A + (size_t)(bm + r) * K + k0 + c);
            bv[i] = *(const uint4*)(g_Wh + (size_t)(bn + r) * K + k0 + c);
        }
        __syncthreads();
        #pragma unroll
        for (int i = 0; i < 2; i++) {
            int f = tid + i * 256;
            int r = f >> 2, c = (f & 3) * 8;
            *(uint4*)&As[r][c] = av[i];
            *(uint4*)&Bs[r][c] = bv[i];
        }
        __syncthreads();
        #pragma unroll
        for (int ks = 0; ks < 32; ks += 16) {
            unsigned a[2][4], b[8][2];
            #pragma unroll
            for (int mt = 0; mt < 2; mt++) {
                int r0 = warp_m + mt * 16 + g;
                a[mt][0] = *(const unsigned*)&As[r0][ks + 2 * q];
                a[mt][1] = *(const unsigned*)&As[r0 + 8][ks + 2 * q];
                a[mt][2] = *(const unsigned*)&As[r0][ks + 2 * q + 8];
                a[mt][3] = *(const unsigned*)&As[r0 + 8][ks + 2 * q + 8];
            }
            #pragma unroll
            for (int nt = 0; nt < 8; nt++) {
                int c = warp_n + nt * 8 + g;
                b[nt][0] = *(const unsigned*)&Bs[c][ks + 2 * q];
                b[nt][1] = *(const unsigned*)&Bs[c][ks + 2 * q + 8];
            }
            #pragma unroll
            for (int mt = 0; mt < 2; mt++)
                #pragma unroll
                for (int nt = 0; nt < 8; nt++) {
                    float* cr = acc[mt][nt];
                    asm volatile(
                        "mma.sync.aligned.m16n8k16.row.col.f32.f16.f16.f32 "
                        "{%0,%1,%2,%3}, {%4,%5,%6,%7}, {%8,%9}, {%0,%1,%2,%3};\n"
                        : "+f"(cr[0]), "+f"(cr[1]), "+f"(cr[2]), "+f"(cr[3])
                        : "r"(a[mt][0]), "r"(a[mt][1]), "r"(a[mt][2]), "r"(a[mt][3]),
                          "r"(b[nt][0]), "r"(b[nt][1]));
                }
        }
    }
    // epilogue: bias + optional relu, fp16 output
    #pragma unroll
    for (int mt = 0; mt < 2; mt++) {
        int r0 = bm + warp_m + mt * 16 + g;
        #pragma unroll
        for (int nt = 0; nt < 8; nt++) {
            int c0 = bn + warp_n + nt * 8 + 2 * q;
            float bi0 = g_bias[c0], bi1 = g_bias[c0 + 1];
            if (r0 < M) {
                float v0 = acc[mt][nt][0] + bi0, v1 = acc[mt][nt][1] + bi1;
                if (RELU) { v0 = fmaxf(v0, 0.f); v1 = fmaxf(v1, 0.f); }
                *(__half2*)(C + (size_t)r0 * ldc + c0) = __floats2half2_rn(v0, v1);
            }
            if (r0 + 8 < M) {
                float v2 = acc[mt][nt][2] + bi0, v3 = acc[mt][nt][3] + bi1;
                if (RELU) { v2 = fmaxf(v2, 0.f); v3 = fmaxf(v3, 0.f); }
                *(__half2*)(C + (size_t)(r0 + 8) * ldc + c0) = __floats2half2_rn(v2, v3);
            }
        }
    }
}

// ---------------- per-edge prediction: warp handles EPW edges, W4 in registers ----------------
__global__ void k_edge(const float* __restrict__ W4, const float* __restrict__ b4,
                       float* __restrict__ out) {
    int tid = threadIdx.x, lane = tid & 31;
    int warp = (blockIdx.x * blockDim.x + tid) >> 5;
    float4 w0 = ((const float4*)W4)[lane * 2];
    float4 w1 = ((const float4*)W4)[lane * 2 + 1];
    float bb = b4[0];
    const __half2 hz = __floats2half2_rn(0.f, 0.f);
    int base = warp * EPW;
    #pragma unroll
    for (int i = 0; i < EPW; i++) {
        int p = base + i;
        if (p >= EE) return;
        int2 v = g_e2[p];
        int s = v.x & 0xffff;
        int d = (int)(((unsigned)v.x) >> 16);
        const uint4* Ar = (const uint4*)(g_ABh + (size_t)s * 512);
        const uint4* Br = (const uint4*)(g_ABh + (size_t)d * 512 + 256);
        uint4 a = Ar[lane];
        uint4 b = Br[lane];
        __half2 t0 = __hmax2(__hadd2(*(__half2*)&a.x, *(__half2*)&b.x), hz);
        __half2 t1 = __hmax2(__hadd2(*(__half2*)&a.y, *(__half2*)&b.y), hz);
        __half2 t2 = __hmax2(__hadd2(*(__half2*)&a.z, *(__half2*)&b.z), hz);
        __half2 t3 = __hmax2(__hadd2(*(__half2*)&a.w, *(__half2*)&b.w), hz);
        float2 f0 = __half22float2(t0), f1 = __half22float2(t1);
        float2 f2 = __half22float2(t2), f3 = __half22float2(t3);
        float acc = f0.x * w0.x + f0.y * w0.y + f1.x * w0.z + f1.y * w0.w +
                    f2.x * w1.x + f2.y * w1.y + f3.x * w1.z + f3.y * w1.w;
        #pragma unroll
        for (int o = 16; o; o >>= 1) acc += __shfl_down_sync(0xffffffffu, acc, o);
        if (lane == 0) out[v.y] = acc + bb;
    }
}

// ---------------- launch ----------------
extern "C" void kernel_launch(void* const* d_in, const int* in_sizes, int n_in,
                              void* d_out, int out_size) {
    const float* x   = (const float*)d_in[0];
    const int*   ei  = (const int*)d_in[1];   // dtype sniffed at runtime (int32 vs int64)
    const float* W1l = (const float*)d_in[2];
    const float* b1l = (const float*)d_in[3];
    const float* W1r = (const float*)d_in[4];
    const float* W2l = (const float*)d_in[5];
    const float* b2l = (const float*)d_in[6];
    const float* W2r = (const float*)d_in[7];
    const float* W3  = (const float*)d_in[8];
    const float* b3  = (const float*)d_in[9];
    const float* W4  = (const float*)d_in[10];
    const float* b4  = (const float*)d_in[11];
    float* out = (float*)d_out;

    __half *p_xh, *p_cath, *p_h1h, *p_h2h, *p_ABh;
    cudaGetSymbolAddress((void**)&p_xh,   g_xh);
    cudaGetSymbolAddress((void**)&p_cath, g_cath);
    cudaGetSymbolAddress((void**)&p_h1h,  g_h1h);
    cudaGetSymbolAddress((void**)&p_h2h,  g_h2h);
    cudaGetSymbolAddress((void**)&p_ABh,  g_ABh);

    const int TB = 256;
    // CSR build + x fp16 conversion
    k_detect<<<1, 256>>>(ei);
    k_init<<<(NN + TB - 1) / TB, TB>>>();
    k_count<<<(EE + TB - 1) / TB, TB>>>(ei);
    k_half<<<(NN * 128 / 8 + TB - 1) / TB, TB>>>(x);
    k_bsum<<<NBLK, SCAN_B>>>();
    k_bscan<<<1, 256>>>();
    k_scan2<<<NBLK, SCAN_B>>>();
    k_fill<<<(EE + TB - 1) / TB, TB>>>();

    const int aggGrid = (NN * 32 + TB - 1) / TB;
    const int mTiles  = (NN + 127) / 128;   // 391

    // SAGE layer 1: h1 = relu([mean_agg(x)|x] @ [W1l;W1r] + b1l)
    k_agg<<<aggGrid, TB>>>(p_xh, p_xh);
    k_pack2h<<<(128 * 256 + TB - 1) / TB, TB>>>(W1l, W1r);
    k_packbias<<<1, 128>>>(b1l, 128, 128);
    gemm_h<true><<<dim3(1, mTiles), 256>>>(p_cath, NN, 256, p_h1h, 128);

    // SAGE layer 2
    k_agg<<<aggGrid, TB>>>(p_h1h, p_h1h);
    k_pack2h<<<(128 * 256 + TB - 1) / TB, TB>>>(W2l, W2r);
    k_packbias<<<1, 128>>>(b2l, 128, 128);
    gemm_h<true><<<dim3(1, mTiles), 256>>>(p_cath, NN, 256, p_h2h, 128);

    // Edge-MLP factorization: ABh[:,0:256] = h2@W3_top + b3, ABh[:,256:512] = h2@W3_bot
    k_packw3h<<<(512 * 128 + TB - 1) / TB, TB>>>(W3);
    k_packbias<<<(512 + TB - 1) / TB, TB>>>(b3, 256, 512);
    gemm_h<false><<<dim3(4, mTiles), 256>>>(p_h2h, NN, 128, p_ABh, 512);

    // Per-edge: dot(relu(A[src]+B[dst]), W4) + b4 (dst-grouped CSR order, EPW edges/warp)
    const int edgeWarps = (EE + EPW - 1) / EPW;
    k_edge<<<(edgeWarps * 32 + TB - 1) / TB, TB>>>(W4, b4, out);
}